// round 11
// baseline (speedup 1.0000x reference)
#include <cuda_runtime.h>
#include <math.h>

#define BB 2
#define CC 2
#define NN 1024
#define HH 8
#define FF 64
#define BCH (BB*CC*HH)   // 32 head-instances
#define K2 (HH*FF)       // 512

// ---------------- scratch (device globals; no runtime allocation) ----------
__device__ float    g_hp[BCH * NN * FF];          // h_prime, reused for both layers (8MB)
__device__ float    g_s [BCH * NN];
__device__ float    g_d [BCH * NN];
__device__ float    g_x1[BB * CC * NN * K2];      // layer-1 output, permuted+elu (8MB)
__device__ float    g_o2[BCH * NN * FF];          // layer-2 pre-mean output (8MB)
__device__ unsigned g_mask[BB * NN * (NN / 32)];  // edge bitmask (256KB)

// ---------------- adjacency -> bitmask (with self loops) -------------------
__global__ void mask_kernel(const int* __restrict__ adj) {
    int bn = blockIdx.x;          // b*NN + n
    int m  = threadIdx.x;         // 0..1023
    int n  = bn & (NN - 1);
    bool edge = (adj[(size_t)bn * NN + m] != 0) || (m == n);
    unsigned word = __ballot_sync(0xffffffffu, edge);
    if ((m & 31) == 0) g_mask[bn * 32 + (m >> 5)] = word;
}

// ---------------- GEMM + tanh + a_src/a_dst epilogue -----------------------
// h_prime[e, n, f] = sum_k X[bc, n, k] * W[ch, k, f]
// s[e,n] = sum_f tanh(h_prime) * a_src[ch,f];  d likewise.
template<int K>
__global__ __launch_bounds__(256) void gemm_kernel(
    const float* __restrict__ Xext,
    const float* __restrict__ W,
    const float* __restrict__ a_src,
    const float* __restrict__ a_dst,
    int use_x1)
{
    const float* X = use_x1 ? g_x1 : Xext;

    const int e  = blockIdx.y;           // 0..31
    const int n0 = blockIdx.x * 64;
    const int b  = e / (CC * HH);
    const int c  = (e / HH) % CC;
    const int h  = e % HH;
    const int bc = b * CC + c;
    const int ch = c * HH + h;

    __shared__ __align__(16) float Xs[64 * 68];
    __shared__ __align__(16) float Ws[64 * 68];
    __shared__ float As[FF], Ad[FF];

    const int tid = threadIdx.x;
    const int r   = tid >> 2;            // 0..63 output row in tile
    const int tq  = tid & 3;             // feature quarter

    if (tid < FF) {
        As[tid] = a_src[ch * FF + tid];
        Ad[tid] = a_dst[ch * FF + tid];
    }

    float4 acc[4];
    #pragma unroll
    for (int q = 0; q < 4; q++) acc[q] = make_float4(0.f, 0.f, 0.f, 0.f);

    const float* Xrow  = X + ((size_t)bc * NN + n0) * K;
    const float* Wbase = W + (size_t)ch * K * FF;

    for (int kc = 0; kc < K; kc += 64) {
        #pragma unroll
        for (int i = 0; i < 4; i++) {
            int idx = tid + i * 256;
            int row = idx >> 4;
            int c4  = idx & 15;
            float4 xv = *(const float4*)(Xrow + (size_t)row * K + kc + c4 * 4);
            *(float4*)(Xs + row * 68 + c4 * 4) = xv;
            float4 wv = *(const float4*)(Wbase + (size_t)(kc + row) * FF + c4 * 4);
            *(float4*)(Ws + row * 68 + c4 * 4) = wv;
        }
        __syncthreads();

        #pragma unroll 16
        for (int k = 0; k < 64; k++) {
            float xv = Xs[r * 68 + k];
            const float4* wr = (const float4*)(Ws + k * 68);
            #pragma unroll
            for (int q = 0; q < 4; q++) {
                float4 wv = wr[tq * 4 + q];
                acc[q].x += xv * wv.x;
                acc[q].y += xv * wv.y;
                acc[q].z += xv * wv.z;
                acc[q].w += xv * wv.w;
            }
        }
        __syncthreads();
    }

    // epilogue: tanh + per-row dot with a_src/a_dst
    float sp = 0.f, dp = 0.f;
    #pragma unroll
    for (int q = 0; q < 4; q++) {
        int f = tq * 16 + q * 4;
        float t0 = tanhf(acc[q].x);
        float t1 = tanhf(acc[q].y);
        float t2 = tanhf(acc[q].z);
        float t3 = tanhf(acc[q].w);
        sp += t0 * As[f] + t1 * As[f + 1] + t2 * As[f + 2] + t3 * As[f + 3];
        dp += t0 * Ad[f] + t1 * Ad[f + 1] + t2 * Ad[f + 2] + t3 * Ad[f + 3];
    }
    sp += __shfl_xor_sync(0xffffffffu, sp, 1);
    sp += __shfl_xor_sync(0xffffffffu, sp, 2);
    dp += __shfl_xor_sync(0xffffffffu, dp, 1);
    dp += __shfl_xor_sync(0xffffffffu, dp, 2);

    const int n = n0 + r;
    if (tq == 0) {
        g_s[e * NN + n] = sp;
        g_d[e * NN + n] = dp;
    }
    float4* hp = (float4*)(g_hp + ((size_t)e * NN + n) * FF);
    #pragma unroll
    for (int q = 0; q < 4; q++) hp[tq * 4 + q] = acc[q];
}

// ---------------- fused attention: softmax(LR(s[n]+d[m]), mask) @ h_prime --
__global__ __launch_bounds__(256) void attn_kernel(int layer)
{
    const int e  = blockIdx.y;
    const int n0 = blockIdx.x * 64;
    const int b  = e / (CC * HH);
    const int c  = (e / HH) % CC;
    const int h  = e % HH;
    const int bc = b * CC + c;

    __shared__ float    d_sh[NN];          // 4KB
    __shared__ unsigned msk[64 * 32];      // 8KB
    __shared__ __align__(16) float hs[64 * 68];  // 17.4KB
    __shared__ float    ws[64 * 65];       // 16.6KB  (total ~46.3KB)

    const int tid = threadIdx.x;
    const int r   = tid >> 2;
    const int tq  = tid & 3;
    const int n   = n0 + r;

    for (int i = tid; i < NN; i += 256) d_sh[i] = g_d[e * NN + i];
    for (int i = tid; i < 64 * 32; i += 256) {
        int rr = i >> 5, w = i & 31;
        msk[i] = g_mask[((size_t)b * NN + n0 + rr) * 32 + w];
    }
    const float s_r = g_s[e * NN + n];
    __syncthreads();

    // pass 1: row max over unmasked leaky-relu scores
    float mx = -1e30f;
    #pragma unroll 8
    for (int k = 0; k < 256; k++) {
        int m = tq + 4 * k;
        unsigned bit = (msk[r * 32 + (m >> 5)] >> (m & 31)) & 1u;
        if (bit) {
            float sc = s_r + d_sh[m];
            sc = sc >= 0.f ? sc : 0.2f * sc;
            mx = fmaxf(mx, sc);
        }
    }
    mx = fmaxf(mx, __shfl_xor_sync(0xffffffffu, mx, 1));
    mx = fmaxf(mx, __shfl_xor_sync(0xffffffffu, mx, 2));

    // pass 2: sum of exp
    float sum = 0.f;
    #pragma unroll 8
    for (int k = 0; k < 256; k++) {
        int m = tq + 4 * k;
        unsigned bit = (msk[r * 32 + (m >> 5)] >> (m & 31)) & 1u;
        if (bit) {
            float sc = s_r + d_sh[m];
            sc = sc >= 0.f ? sc : 0.2f * sc;
            sum += __expf(sc - mx);
        }
    }
    sum += __shfl_xor_sync(0xffffffffu, sum, 1);
    sum += __shfl_xor_sync(0xffffffffu, sum, 2);
    const float inv = 1.f / sum;

    // pass 3: accumulate weighted h_prime rows, 64-m chunks staged in smem
    float4 acc[4];
    #pragma unroll
    for (int q = 0; q < 4; q++) acc[q] = make_float4(0.f, 0.f, 0.f, 0.f);

    const float* hpbase = g_hp + (size_t)e * NN * FF;

    for (int ci = 0; ci < 16; ci++) {
        int m0 = ci * 64;
        #pragma unroll
        for (int i = 0; i < 4; i++) {
            int idx = tid + i * 256;
            int row = idx >> 4;
            int c4  = idx & 15;
            *(float4*)(hs + row * 68 + c4 * 4) =
                *(const float4*)(hpbase + (size_t)(m0 + row) * FF + c4 * 4);
        }
        #pragma unroll
        for (int k = 0; k < 16; k++) {
            int ml = tq + 4 * k;
            int m  = m0 + ml;
            unsigned bit = (msk[r * 32 + (m >> 5)] >> (m & 31)) & 1u;
            float w = 0.f;
            if (bit) {
                float sc = s_r + d_sh[m];
                sc = sc >= 0.f ? sc : 0.2f * sc;
                w = __expf(sc - mx) * inv;
            }
            ws[r * 65 + ml] = w;
        }
        __syncthreads();

        #pragma unroll 8
        for (int m = 0; m < 64; m++) {
            float w = ws[r * 65 + m];
            const float4* hr = (const float4*)(hs + m * 68);
            #pragma unroll
            for (int q = 0; q < 4; q++) {
                float4 hv = hr[tq * 4 + q];
                acc[q].x += w * hv.x;
                acc[q].y += w * hv.y;
                acc[q].z += w * hv.z;
                acc[q].w += w * hv.w;
            }
        }
        __syncthreads();
    }

    if (layer == 1) {
        // x1[bc, n, h*F + f] = elu(out1)
        float4* o = (float4*)(g_x1 + ((size_t)bc * NN + n) * K2 + h * FF);
        #pragma unroll
        for (int q = 0; q < 4; q++) {
            float4 v = acc[q];
            v.x = v.x > 0.f ? v.x : expm1f(v.x);
            v.y = v.y > 0.f ? v.y : expm1f(v.y);
            v.z = v.z > 0.f ? v.z : expm1f(v.z);
            v.w = v.w > 0.f ? v.w : expm1f(v.w);
            o[tq * 4 + q] = v;
        }
    } else {
        float4* o = (float4*)(g_o2 + ((size_t)e * NN + n) * FF);
        #pragma unroll
        for (int q = 0; q < 4; q++) o[tq * 4 + q] = acc[q];
    }
}

// ---------------- mean over heads ------------------------------------------
__global__ void mean_kernel(float* __restrict__ out) {
    int idx = blockIdx.x * 256 + threadIdx.x;   // 0..262143
    int f   = idx & 63;
    int n   = (idx >> 6) & 1023;
    int bc  = idx >> 16;
    float sum = 0.f;
    #pragma unroll
    for (int h = 0; h < HH; h++)
        sum += g_o2[(((size_t)bc * HH + h) * NN + n) * FF + f];
    out[idx] = sum * 0.125f;
}

// ---------------- launch ----------------------------------------------------
extern "C" void kernel_launch(void* const* d_in, const int* in_sizes, int n_in,
                              void* d_out, int out_size) {
    const float* x   = (const float*)d_in[0];
    const int*   adj = (const int*)  d_in[1];
    const float* w1  = (const float*)d_in[2];
    const float* as1 = (const float*)d_in[3];
    const float* ad1 = (const float*)d_in[4];
    const float* w2  = (const float*)d_in[5];
    const float* as2 = (const float*)d_in[6];
    const float* ad2 = (const float*)d_in[7];
    float* out = (float*)d_out;

    mask_kernel<<<BB * NN, 1024>>>(adj);

    dim3 grid(NN / 64, BCH);   // (16, 32)
    gemm_kernel<64><<<grid, 256>>>(x, w1, as1, ad1, 0);
    attn_kernel<<<grid, 256>>>(1);
    gemm_kernel<K2><<<grid, 256>>>(nullptr, w2, as2, ad2, 1);
    attn_kernel<<<grid, 256>>>(2);
    mean_kernel<<<(BB * CC * NN * FF) / 256, 256>>>(out);
}

// round 12
// speedup vs baseline: 1.0022x; 1.0022x over previous
#include <cuda_runtime.h>
#include <math.h>

#define BB 2
#define CC 2
#define NN 1024
#define HH 8
#define FF 64
#define BCH (BB*CC*HH)   // 32 head-instances
#define K2 (HH*FF)       // 512

// ---------------- scratch (device globals; no runtime allocation) ----------
__device__ float    g_hp[BCH * NN * FF];          // h_prime, reused for both layers (8MB)
__device__ float    g_s [BCH * NN];
__device__ float    g_d [BCH * NN];
__device__ float    g_x1[BB * CC * NN * K2];      // layer-1 output, permuted+elu (8MB)
__device__ float    g_o2[BCH * NN * FF];          // layer-2 pre-mean output (8MB)
__device__ unsigned g_mask[BB * NN * (NN / 32)];  // edge bitmask (256KB)

// ---------------- adjacency -> bitmask (with self loops) -------------------
__global__ void mask_kernel(const int* __restrict__ adj) {
    int bn = blockIdx.x;          // b*NN + n
    int m  = threadIdx.x;         // 0..1023
    int n  = bn & (NN - 1);
    bool edge = (adj[(size_t)bn * NN + m] != 0) || (m == n);
    unsigned word = __ballot_sync(0xffffffffu, edge);
    if ((m & 31) == 0) g_mask[bn * 32 + (m >> 5)] = word;
}

// ---------------- GEMM + tanh + a_src/a_dst epilogue -----------------------
// h_prime[e, n, f] = sum_k X[bc, n, k] * W[ch, k, f]
// s[e,n] = sum_f tanh(h_prime) * a_src[ch,f];  d likewise.
template<int K>
__global__ __launch_bounds__(256) void gemm_kernel(
    const float* __restrict__ Xext,
    const float* __restrict__ W,
    const float* __restrict__ a_src,
    const float* __restrict__ a_dst,
    int use_x1)
{
    const float* X = use_x1 ? g_x1 : Xext;

    const int e  = blockIdx.y;           // 0..31
    const int n0 = blockIdx.x * 64;
    const int b  = e / (CC * HH);
    const int c  = (e / HH) % CC;
    const int h  = e % HH;
    const int bc = b * CC + c;
    const int ch = c * HH + h;

    __shared__ __align__(16) float Xs[64 * 68];
    __shared__ __align__(16) float Ws[64 * 68];
    __shared__ float As[FF], Ad[FF];

    const int tid = threadIdx.x;
    const int r   = tid >> 2;            // 0..63 output row in tile
    const int tq  = tid & 3;             // feature quarter

    if (tid < FF) {
        As[tid] = a_src[ch * FF + tid];
        Ad[tid] = a_dst[ch * FF + tid];
    }

    float4 acc[4];
    #pragma unroll
    for (int q = 0; q < 4; q++) acc[q] = make_float4(0.f, 0.f, 0.f, 0.f);

    const float* Xrow  = X + ((size_t)bc * NN + n0) * K;
    const float* Wbase = W + (size_t)ch * K * FF;

    for (int kc = 0; kc < K; kc += 64) {
        #pragma unroll
        for (int i = 0; i < 4; i++) {
            int idx = tid + i * 256;
            int row = idx >> 4;
            int c4  = idx & 15;
            float4 xv = *(const float4*)(Xrow + (size_t)row * K + kc + c4 * 4);
            *(float4*)(Xs + row * 68 + c4 * 4) = xv;
            float4 wv = *(const float4*)(Wbase + (size_t)(kc + row) * FF + c4 * 4);
            *(float4*)(Ws + row * 68 + c4 * 4) = wv;
        }
        __syncthreads();

        #pragma unroll 16
        for (int k = 0; k < 64; k++) {
            float xv = Xs[r * 68 + k];
            const float4* wr = (const float4*)(Ws + k * 68);
            #pragma unroll
            for (int q = 0; q < 4; q++) {
                float4 wv = wr[tq * 4 + q];
                acc[q].x += xv * wv.x;
                acc[q].y += xv * wv.y;
                acc[q].z += xv * wv.z;
                acc[q].w += xv * wv.w;
            }
        }
        __syncthreads();
    }

    // epilogue: tanh + per-row dot with a_src/a_dst
    float sp = 0.f, dp = 0.f;
    #pragma unroll
    for (int q = 0; q < 4; q++) {
        int f = tq * 16 + q * 4;
        float t0 = tanhf(acc[q].x);
        float t1 = tanhf(acc[q].y);
        float t2 = tanhf(acc[q].z);
        float t3 = tanhf(acc[q].w);
        sp += t0 * As[f] + t1 * As[f + 1] + t2 * As[f + 2] + t3 * As[f + 3];
        dp += t0 * Ad[f] + t1 * Ad[f + 1] + t2 * Ad[f + 2] + t3 * Ad[f + 3];
    }
    sp += __shfl_xor_sync(0xffffffffu, sp, 1);
    sp += __shfl_xor_sync(0xffffffffu, sp, 2);
    dp += __shfl_xor_sync(0xffffffffu, dp, 1);
    dp += __shfl_xor_sync(0xffffffffu, dp, 2);

    const int n = n0 + r;
    if (tq == 0) {
        g_s[e * NN + n] = sp;
        g_d[e * NN + n] = dp;
    }
    float4* hp = (float4*)(g_hp + ((size_t)e * NN + n) * FF);
    #pragma unroll
    for (int q = 0; q < 4; q++) hp[tq * 4 + q] = acc[q];
}

// ---------------- fused attention: softmax(LR(s[n]+d[m]), mask) @ h_prime --
__global__ __launch_bounds__(256) void attn_kernel(int layer)
{
    const int e  = blockIdx.y;
    const int n0 = blockIdx.x * 64;
    const int b  = e / (CC * HH);
    const int c  = (e / HH) % CC;
    const int h  = e % HH;
    const int bc = b * CC + c;

    __shared__ float    d_sh[NN];          // 4KB
    __shared__ unsigned msk[64 * 32];      // 8KB
    __shared__ __align__(16) float hs[64 * 68];  // 17.4KB
    __shared__ float    ws[64 * 65];       // 16.6KB  (total ~46.3KB)

    const int tid = threadIdx.x;
    const int r   = tid >> 2;
    const int tq  = tid & 3;
    const int n   = n0 + r;

    for (int i = tid; i < NN; i += 256) d_sh[i] = g_d[e * NN + i];
    for (int i = tid; i < 64 * 32; i += 256) {
        int rr = i >> 5, w = i & 31;
        msk[i] = g_mask[((size_t)b * NN + n0 + rr) * 32 + w];
    }
    const float s_r = g_s[e * NN + n];
    __syncthreads();

    // pass 1: row max over unmasked leaky-relu scores
    float mx = -1e30f;
    #pragma unroll 8
    for (int k = 0; k < 256; k++) {
        int m = tq + 4 * k;
        unsigned bit = (msk[r * 32 + (m >> 5)] >> (m & 31)) & 1u;
        if (bit) {
            float sc = s_r + d_sh[m];
            sc = sc >= 0.f ? sc : 0.2f * sc;
            mx = fmaxf(mx, sc);
        }
    }
    mx = fmaxf(mx, __shfl_xor_sync(0xffffffffu, mx, 1));
    mx = fmaxf(mx, __shfl_xor_sync(0xffffffffu, mx, 2));

    // pass 2: sum of exp
    float sum = 0.f;
    #pragma unroll 8
    for (int k = 0; k < 256; k++) {
        int m = tq + 4 * k;
        unsigned bit = (msk[r * 32 + (m >> 5)] >> (m & 31)) & 1u;
        if (bit) {
            float sc = s_r + d_sh[m];
            sc = sc >= 0.f ? sc : 0.2f * sc;
            sum += __expf(sc - mx);
        }
    }
    sum += __shfl_xor_sync(0xffffffffu, sum, 1);
    sum += __shfl_xor_sync(0xffffffffu, sum, 2);
    const float inv = 1.f / sum;

    // pass 3: accumulate weighted h_prime rows, 64-m chunks staged in smem
    float4 acc[4];
    #pragma unroll
    for (int q = 0; q < 4; q++) acc[q] = make_float4(0.f, 0.f, 0.f, 0.f);

    const float* hpbase = g_hp + (size_t)e * NN * FF;

    for (int ci = 0; ci < 16; ci++) {
        int m0 = ci * 64;
        #pragma unroll
        for (int i = 0; i < 4; i++) {
            int idx = tid + i * 256;
            int row = idx >> 4;
            int c4  = idx & 15;
            *(float4*)(hs + row * 68 + c4 * 4) =
                *(const float4*)(hpbase + (size_t)(m0 + row) * FF + c4 * 4);
        }
        #pragma unroll
        for (int k = 0; k < 16; k++) {
            int ml = tq + 4 * k;
            int m  = m0 + ml;
            unsigned bit = (msk[r * 32 + (m >> 5)] >> (m & 31)) & 1u;
            float w = 0.f;
            if (bit) {
                float sc = s_r + d_sh[m];
                sc = sc >= 0.f ? sc : 0.2f * sc;
                w = __expf(sc - mx) * inv;
            }
            ws[r * 65 + ml] = w;
        }
        __syncthreads();

        #pragma unroll 8
        for (int m = 0; m < 64; m++) {
            float w = ws[r * 65 + m];
            const float4* hr = (const float4*)(hs + m * 68);
            #pragma unroll
            for (int q = 0; q < 4; q++) {
                float4 hv = hr[tq * 4 + q];
                acc[q].x += w * hv.x;
                acc[q].y += w * hv.y;
                acc[q].z += w * hv.z;
                acc[q].w += w * hv.w;
            }
        }
        __syncthreads();
    }

    if (layer == 1) {
        // x1[bc, n, h*F + f] = elu(out1)
        float4* o = (float4*)(g_x1 + ((size_t)bc * NN + n) * K2 + h * FF);
        #pragma unroll
        for (int q = 0; q < 4; q++) {
            float4 v = acc[q];
            v.x = v.x > 0.f ? v.x : expm1f(v.x);
            v.y = v.y > 0.f ? v.y : expm1f(v.y);
            v.z = v.z > 0.f ? v.z : expm1f(v.z);
            v.w = v.w > 0.f ? v.w : expm1f(v.w);
            o[tq * 4 + q] = v;
        }
    } else {
        float4* o = (float4*)(g_o2 + ((size_t)e * NN + n) * FF);
        #pragma unroll
        for (int q = 0; q < 4; q++) o[tq * 4 + q] = acc[q];
    }
}

// ---------------- mean over heads ------------------------------------------
__global__ void mean_kernel(float* __restrict__ out) {
    int idx = blockIdx.x * 256 + threadIdx.x;   // 0..262143
    int f   = idx & 63;
    int n   = (idx >> 6) & 1023;
    int bc  = idx >> 16;
    float sum = 0.f;
    #pragma unroll
    for (int h = 0; h < HH; h++)
        sum += g_o2[(((size_t)bc * HH + h) * NN + n) * FF + f];
    out[idx] = sum * 0.125f;
}

// ---------------- launch ----------------------------------------------------
extern "C" void kernel_launch(void* const* d_in, const int* in_sizes, int n_in,
                              void* d_out, int out_size) {
    const float* x   = (const float*)d_in[0];
    const int*   adj = (const int*)  d_in[1];
    const float* w1  = (const float*)d_in[2];
    const float* as1 = (const float*)d_in[3];
    const float* ad1 = (const float*)d_in[4];
    const float* w2  = (const float*)d_in[5];
    const float* as2 = (const float*)d_in[6];
    const float* ad2 = (const float*)d_in[7];
    float* out = (float*)d_out;

    mask_kernel<<<BB * NN, 1024>>>(adj);

    dim3 grid(NN / 64, BCH);   // (16, 32)
    gemm_kernel<64><<<grid, 256>>>(x, w1, as1, ad1, 0);
    attn_kernel<<<grid, 256>>>(1);
    gemm_kernel<K2><<<grid, 256>>>(nullptr, w2, as2, ad2, 1);
    attn_kernel<<<grid, 256>>>(2);
    mean_kernel<<<(BB * CC * NN * FF) / 256, 256>>>(out);
}

// round 14
// speedup vs baseline: 4.3930x; 4.3831x over previous
#include <cuda_runtime.h>
#include <math.h>

#define BB 2
#define CC 2
#define NN 1024
#define HH 8
#define FF 64
#define BCH (BB*CC*HH)   // 32 head-instances
#define K2 (HH*FF)       // 512

// ---------------- scratch (device globals; no runtime allocation) ----------
__device__ float    g_hp[BCH * NN * FF];          // h_prime (8MB)
__device__ float    g_s [BCH * NN];
__device__ float    g_d [BCH * NN];
__device__ float    g_x1[BB * CC * NN * K2];      // layer-1 output, permuted+elu (8MB)
__device__ float    g_o2[BCH * NN * FF];          // layer-2 pre-mean output (8MB)
__device__ unsigned g_mask[BB * NN * (NN / 32)];  // edge bitmask (256KB)

// smem sizes (floats)
#define GEMM_WS   (64 * 68)      // Ws[k][f], stride 68 (16B aligned, cf-free LDS.128)
#define GEMM_XS   (128 * 66)     // Xs[n][k], stride 66 (odd*2 -> 4 distinct banks for row bcast)
#define GEMM_SMEM ((GEMM_WS + GEMM_XS + 128) * 4)

#define ATTN_HS   (64 * 68)      // hs[m][f]
#define ATTN_WS   (128 * 65)     // ws[r][m], stride 65
#define ATTN_SMEM ((ATTN_HS + ATTN_WS + 1024 + 128) * 4 + 128 * 32 * 4)

// ---------------- adjacency -> bitmask (with self loops) -------------------
__global__ void mask_kernel(const int* __restrict__ adj) {
    int bn = blockIdx.x;          // b*NN + n
    int m  = threadIdx.x;         // 0..1023
    int n  = bn & (NN - 1);
    bool edge = (adj[(size_t)bn * NN + m] != 0) || (m == n);
    unsigned word = __ballot_sync(0xffffffffu, edge);
    if ((m & 31) == 0) g_mask[bn * 32 + (m >> 5)] = word;
}

// ---------------- GEMM + tanh + a_src/a_dst epilogue -----------------------
// 128-row x 64-col tile, 256 threads, each thread 4 rows x 8 cols (two 4-col chunks)
template<int K>
__global__ __launch_bounds__(256) void gemm_kernel(
    const float* __restrict__ Xext,
    const float* __restrict__ W,
    const float* __restrict__ a_src,
    const float* __restrict__ a_dst,
    int use_x1)
{
    extern __shared__ float sm[];
    float* Ws = sm;                    // [64][68]
    float* Xs = sm + GEMM_WS;          // [128][66]
    float* As = Xs + GEMM_XS;          // [64]
    float* Ad = As + 64;               // [64]

    const float* X = use_x1 ? g_x1 : Xext;

    const int e  = blockIdx.y;                 // 0..31
    const int n0 = blockIdx.x * 128;
    const int b  = e / (CC * HH);
    const int c  = (e / HH) % CC;
    const int h  = e % HH;
    const int bc = b * CC + c;
    const int ch = c * HH + h;

    const int tid = threadIdx.x;
    const int tx  = tid & 7;          // col group: cols tx*4 and 32+tx*4
    const int ty  = tid >> 3;         // row group: rows ty*4 .. ty*4+3
    const int r0  = ty * 4;
    const int f0  = tx * 4;
    const int f1  = 32 + tx * 4;

    if (tid < 64) {
        As[tid] = a_src[ch * FF + tid];
        Ad[tid] = a_dst[ch * FF + tid];
    }

    float4 acc0[4], acc1[4];
    #pragma unroll
    for (int i = 0; i < 4; i++) { acc0[i] = make_float4(0.f,0.f,0.f,0.f); acc1[i] = make_float4(0.f,0.f,0.f,0.f); }

    const float* Xbase = X + ((size_t)bc * NN + n0) * K;
    const float* Wbase = W + (size_t)ch * K * FF;

    for (int kc = 0; kc < K; kc += 64) {
        if (kc) __syncthreads();
        // load Xs: 128 rows x 64 k = 2048 float4, 8 per thread (scalar STS, stride 66)
        #pragma unroll
        for (int t = 0; t < 8; t++) {
            int idx = tid + t * 256;
            int row = idx >> 4;
            int c4  = idx & 15;
            float4 v = *(const float4*)(Xbase + (size_t)row * K + kc + c4 * 4);
            float* p = Xs + row * 66 + c4 * 4;
            p[0] = v.x; p[1] = v.y; p[2] = v.z; p[3] = v.w;
        }
        // load Ws: 64 x 64 = 1024 float4, 4 per thread (STS.128, stride 68)
        #pragma unroll
        for (int t = 0; t < 4; t++) {
            int idx = tid + t * 256;
            int row = idx >> 4;
            int c4  = idx & 15;
            *(float4*)(Ws + row * 68 + c4 * 4) =
                *(const float4*)(Wbase + (size_t)(kc + row) * FF + c4 * 4);
        }
        __syncthreads();

        #pragma unroll 16
        for (int k = 0; k < 64; k++) {
            float4 w0 = *(const float4*)(Ws + k * 68 + f0);
            float4 w1 = *(const float4*)(Ws + k * 68 + f1);
            float x0 = Xs[(r0 + 0) * 66 + k];
            float x1 = Xs[(r0 + 1) * 66 + k];
            float x2 = Xs[(r0 + 2) * 66 + k];
            float x3 = Xs[(r0 + 3) * 66 + k];
            acc0[0].x += x0*w0.x; acc0[0].y += x0*w0.y; acc0[0].z += x0*w0.z; acc0[0].w += x0*w0.w;
            acc1[0].x += x0*w1.x; acc1[0].y += x0*w1.y; acc1[0].z += x0*w1.z; acc1[0].w += x0*w1.w;
            acc0[1].x += x1*w0.x; acc0[1].y += x1*w0.y; acc0[1].z += x1*w0.z; acc0[1].w += x1*w0.w;
            acc1[1].x += x1*w1.x; acc1[1].y += x1*w1.y; acc1[1].z += x1*w1.z; acc1[1].w += x1*w1.w;
            acc0[2].x += x2*w0.x; acc0[2].y += x2*w0.y; acc0[2].z += x2*w0.z; acc0[2].w += x2*w0.w;
            acc1[2].x += x2*w1.x; acc1[2].y += x2*w1.y; acc1[2].z += x2*w1.z; acc1[2].w += x2*w1.w;
            acc0[3].x += x3*w0.x; acc0[3].y += x3*w0.y; acc0[3].z += x3*w0.z; acc0[3].w += x3*w0.w;
            acc1[3].x += x3*w1.x; acc1[3].y += x3*w1.y; acc1[3].z += x3*w1.z; acc1[3].w += x3*w1.w;
        }
    }

    // epilogue: tanh + per-row dot with a_src/a_dst, reduce over tx lanes
    float4 as0 = *(const float4*)(As + f0);
    float4 as1 = *(const float4*)(As + f1);
    float4 ad0 = *(const float4*)(Ad + f0);
    float4 ad1 = *(const float4*)(Ad + f1);

    #pragma unroll
    for (int i = 0; i < 4; i++) {
        float t0 = tanhf(acc0[i].x), t1 = tanhf(acc0[i].y), t2 = tanhf(acc0[i].z), t3 = tanhf(acc0[i].w);
        float u0 = tanhf(acc1[i].x), u1 = tanhf(acc1[i].y), u2 = tanhf(acc1[i].z), u3 = tanhf(acc1[i].w);
        float sp = t0*as0.x + t1*as0.y + t2*as0.z + t3*as0.w
                 + u0*as1.x + u1*as1.y + u2*as1.z + u3*as1.w;
        float dp = t0*ad0.x + t1*ad0.y + t2*ad0.z + t3*ad0.w
                 + u0*ad1.x + u1*ad1.y + u2*ad1.z + u3*ad1.w;
        sp += __shfl_xor_sync(0xffffffffu, sp, 1);
        sp += __shfl_xor_sync(0xffffffffu, sp, 2);
        sp += __shfl_xor_sync(0xffffffffu, sp, 4);
        dp += __shfl_xor_sync(0xffffffffu, dp, 1);
        dp += __shfl_xor_sync(0xffffffffu, dp, 2);
        dp += __shfl_xor_sync(0xffffffffu, dp, 4);
        int n = n0 + r0 + i;
        if (tx == 0) {
            g_s[e * NN + n] = sp;
            g_d[e * NN + n] = dp;
        }
        float* hp = g_hp + ((size_t)e * NN + n) * FF;
        *(float4*)(hp + f0) = acc0[i];
        *(float4*)(hp + f1) = acc1[i];
    }
}

// ---------------- fused attention (unnormalized softmax, single sweep) -----
__global__ __launch_bounds__(256) void attn_kernel(int layer)
{
    extern __shared__ float sm[];
    float*    hs   = sm;                     // [64][68]
    float*    ws   = sm + ATTN_HS;           // [128][65]
    float*    d_sh = ws + ATTN_WS;           // [1024]
    float*    s_sh = d_sh + 1024;            // [128]
    unsigned* msk  = (unsigned*)(s_sh + 128);// [128][32]

    const int e  = blockIdx.y;
    const int n0 = blockIdx.x * 128;
    const int b  = e / (CC * HH);
    const int c  = (e / HH) % CC;
    const int h  = e % HH;
    const int bc = b * CC + c;

    const int tid = threadIdx.x;
    const int tx  = tid & 7;
    const int ty  = tid >> 3;
    const int r0  = ty * 4;
    const int f0  = tx * 4;
    const int f1  = 32 + tx * 4;

    for (int i = tid; i < NN; i += 256) d_sh[i] = g_d[e * NN + i];
    if (tid < 128) s_sh[tid] = g_s[e * NN + n0 + tid];
    for (int i = tid; i < 128 * 32; i += 256) {
        int rr = i >> 5, w = i & 31;
        msk[i] = g_mask[((size_t)b * NN + n0 + rr) * 32 + w];
    }
    __syncthreads();

    float s_r[4];
    #pragma unroll
    for (int i = 0; i < 4; i++) s_r[i] = s_sh[r0 + i];

    float4 acc0[4], acc1[4];
    float  rsum[4];
    #pragma unroll
    for (int i = 0; i < 4; i++) {
        acc0[i] = make_float4(0.f,0.f,0.f,0.f);
        acc1[i] = make_float4(0.f,0.f,0.f,0.f);
        rsum[i] = 0.f;
    }

    const float* hpbase = g_hp + (size_t)e * NN * FF;

    for (int ci = 0; ci < 16; ci++) {
        if (ci) __syncthreads();
        const int m0 = ci * 64;

        // stage h_prime chunk: 64 rows x 64 f, 4 float4 per thread
        #pragma unroll
        for (int t = 0; t < 4; t++) {
            int idx = tid + t * 256;
            int row = idx >> 4;
            int c4  = idx & 15;
            *(float4*)(hs + row * 68 + c4 * 4) =
                *(const float4*)(hpbase + (size_t)(m0 + row) * FF + c4 * 4);
        }

        // P-compute: unnormalized probs into ws[r][m] + per-row sum partials
        #pragma unroll
        for (int i = 0; i < 4; i++) {
            int r = r0 + i;
            unsigned w0 = msk[r * 32 + ci * 2];
            unsigned w1 = msk[r * 32 + ci * 2 + 1];
            float sr = s_r[i];
            #pragma unroll
            for (int j = 0; j < 8; j++) {
                int ml = tx + 8 * j;                     // 0..63
                unsigned word = (ml < 32) ? w0 : w1;
                unsigned bit  = (word >> (ml & 31)) & 1u;
                float sc = sr + d_sh[m0 + ml];
                sc = sc >= 0.f ? sc : 0.2f * sc;
                float p = bit ? __expf(sc) : 0.f;
                rsum[i] += p;
                ws[r * 65 + ml] = p;
            }
        }
        __syncthreads();

        // accumulate: out[r, f] += sum_m P[r,m] * h[m,f]
        #pragma unroll 8
        for (int m = 0; m < 64; m++) {
            float p0 = ws[(r0 + 0) * 65 + m];
            float p1 = ws[(r0 + 1) * 65 + m];
            float p2 = ws[(r0 + 2) * 65 + m];
            float p3 = ws[(r0 + 3) * 65 + m];
            float4 h0 = *(const float4*)(hs + m * 68 + f0);
            float4 h1 = *(const float4*)(hs + m * 68 + f1);
            acc0[0].x += p0*h0.x; acc0[0].y += p0*h0.y; acc0[0].z += p0*h0.z; acc0[0].w += p0*h0.w;
            acc1[0].x += p0*h1.x; acc1[0].y += p0*h1.y; acc1[0].z += p0*h1.z; acc1[0].w += p0*h1.w;
            acc0[1].x += p1*h0.x; acc0[1].y += p1*h0.y; acc0[1].z += p1*h0.z; acc0[1].w += p1*h0.w;
            acc1[1].x += p1*h1.x; acc1[1].y += p1*h1.y; acc1[1].z += p1*h1.z; acc1[1].w += p1*h1.w;
            acc0[2].x += p2*h0.x; acc0[2].y += p2*h0.y; acc0[2].z += p2*h0.z; acc0[2].w += p2*h0.w;
            acc1[2].x += p2*h1.x; acc1[2].y += p2*h1.y; acc1[2].z += p2*h1.z; acc1[2].w += p2*h1.w;
            acc0[3].x += p3*h0.x; acc0[3].y += p3*h0.y; acc0[3].z += p3*h0.z; acc0[3].w += p3*h0.w;
            acc1[3].x += p3*h1.x; acc1[3].y += p3*h1.y; acc1[3].z += p3*h1.z; acc1[3].w += p3*h1.w;
        }
    }

    // per-row sum reduction over the 8 tx lanes -> normalize
    #pragma unroll
    for (int i = 0; i < 4; i++) {
        float s = rsum[i];
        s += __shfl_xor_sync(0xffffffffu, s, 1);
        s += __shfl_xor_sync(0xffffffffu, s, 2);
        s += __shfl_xor_sync(0xffffffffu, s, 4);
        float inv = 1.f / s;
        acc0[i].x *= inv; acc0[i].y *= inv; acc0[i].z *= inv; acc0[i].w *= inv;
        acc1[i].x *= inv; acc1[i].y *= inv; acc1[i].z *= inv; acc1[i].w *= inv;
    }

    if (layer == 1) {
        #pragma unroll
        for (int i = 0; i < 4; i++) {
            int n = n0 + r0 + i;
            float4 v0 = acc0[i], v1 = acc1[i];
            v0.x = v0.x > 0.f ? v0.x : expm1f(v0.x);
            v0.y = v0.y > 0.f ? v0.y : expm1f(v0.y);
            v0.z = v0.z > 0.f ? v0.z : expm1f(v0.z);
            v0.w = v0.w > 0.f ? v0.w : expm1f(v0.w);
            v1.x = v1.x > 0.f ? v1.x : expm1f(v1.x);
            v1.y = v1.y > 0.f ? v1.y : expm1f(v1.y);
            v1.z = v1.z > 0.f ? v1.z : expm1f(v1.z);
            v1.w = v1.w > 0.f ? v1.w : expm1f(v1.w);
            float* o = g_x1 + ((size_t)bc * NN + n) * K2 + h * FF;
            *(float4*)(o + f0) = v0;
            *(float4*)(o + f1) = v1;
        }
    } else {
        #pragma unroll
        for (int i = 0; i < 4; i++) {
            int n = n0 + r0 + i;
            float* o = g_o2 + ((size_t)e * NN + n) * FF;
            *(float4*)(o + f0) = acc0[i];
            *(float4*)(o + f1) = acc1[i];
        }
    }
}

// ---------------- mean over heads ------------------------------------------
__global__ void mean_kernel(float* __restrict__ out) {
    int idx = blockIdx.x * 256 + threadIdx.x;   // 0..262143
    int f   = idx & 63;
    int n   = (idx >> 6) & 1023;
    int bc  = idx >> 16;
    float sum = 0.f;
    #pragma unroll
    for (int h = 0; h < HH; h++)
        sum += g_o2[(((size_t)bc * HH + h) * NN + n) * FF + f];
    out[idx] = sum * 0.125f;
}

// ---------------- launch ----------------------------------------------------
extern "C" void kernel_launch(void* const* d_in, const int* in_sizes, int n_in,
                              void* d_out, int out_size) {
    const float* x   = (const float*)d_in[0];
    const int*   adj = (const int*)  d_in[1];
    const float* w1  = (const float*)d_in[2];
    const float* as1 = (const float*)d_in[3];
    const float* ad1 = (const float*)d_in[4];
    const float* w2  = (const float*)d_in[5];
    const float* as2 = (const float*)d_in[6];
    const float* ad2 = (const float*)d_in[7];
    float* out = (float*)d_out;

    cudaFuncSetAttribute(gemm_kernel<64>,  cudaFuncAttributeMaxDynamicSharedMemorySize, GEMM_SMEM);
    cudaFuncSetAttribute(gemm_kernel<K2>,  cudaFuncAttributeMaxDynamicSharedMemorySize, GEMM_SMEM);
    cudaFuncSetAttribute(attn_kernel,      cudaFuncAttributeMaxDynamicSharedMemorySize, ATTN_SMEM);

    mask_kernel<<<BB * NN, 1024>>>(adj);

    dim3 grid(NN / 128, BCH);   // (8, 32)
    gemm_kernel<64><<<grid, 256, GEMM_SMEM>>>(x, w1, as1, ad1, 0);
    attn_kernel<<<grid, 256, ATTN_SMEM>>>(1);
    gemm_kernel<K2><<<grid, 256, GEMM_SMEM>>>(nullptr, w2, as2, ad2, 1);
    attn_kernel<<<grid, 256, ATTN_SMEM>>>(2);
    mean_kernel<<<(BB * CC * NN * FF) / 256, 256>>>(out);
}